// round 1
// baseline (speedup 1.0000x reference)
#include <cuda_runtime.h>
#include <math.h>

// Problem constants (fixed shapes per setup_inputs)
#define BATCH 8
#define REG   400
#define TLEN  1200
#define NB    5
#define NPSI  1024
#define LMAX  544

// Derived
#define NOUT  TLEN                 // outputs per (b,r,k)
#define GLEN  (TLEN + 1)           // diff-signal length (not materialized)
#define XOFF  288                  // left zero pad in shared X
#define SHX   1824                 // XOFF + 1473 + slack
#define DMAX  576                  // padded D storage per (b,k)

static __device__ float d_INT_PSI[NPSI];
static __device__ float d_D[BATCH * NB][DMAX];
static __device__ int   d_LD[BATCH * NB];   // L + 1 taps of D
static __device__ int   d_OFF[BATCH * NB];  // off - 1
static __device__ float d_SQS[BATCH * NB];  // sqrt(scale)

// ---------------------------------------------------------------------------
// Kernel 1: build INT_PSI = cumsum(exp(-x^2/2)*cos(5x)) * STEP  (fp64 scan)
// ---------------------------------------------------------------------------
__global__ void k_init_psi() {
    __shared__ double sd[NPSI];
    const int i = threadIdx.x;
    const double step = 16.0 / 1023.0;
    double x = -8.0 + step * (double)i;
    double v = exp(-0.5 * x * x) * cos(5.0 * x);
    sd[i] = v;
    __syncthreads();
    // Hillis-Steele inclusive scan
    for (int o = 1; o < NPSI; o <<= 1) {
        double add = (i >= o) ? sd[i - o] : 0.0;
        __syncthreads();
        sd[i] += add;
        __syncthreads();
    }
    d_INT_PSI[i] = (float)(sd[i] * step);
}

// ---------------------------------------------------------------------------
// Kernel 2: per (b,k): scale, mask-prefix length L, D[i]=K[i-1]-K[i],
//           off-1, sqrt(scale), and frequency_bands output.
// One block per (b,k), 576 threads.
// ---------------------------------------------------------------------------
__global__ void k_prep(const float* __restrict__ tr,
                       const float* __restrict__ lsp,
                       const float* __restrict__ bwp,
                       float* __restrict__ out_bands) {
    const int bk = blockIdx.x;
    const int b  = bk / NB;
    const int k  = bk % NB;
    const int i  = threadIdx.x;

    const float STEP_F = (float)(16.0 / 1023.0);
    const float trf    = tr[b] / 2.0f;            // tr_values / REF_TR
    const float scale  = expf(lsp[k]) / trf;      // fp32, matches jnp
    const float sstep  = scale * STEP_F;
    const int   L0     = (int)floorf(scale * 16.0f) + 2;

    __shared__ float shK[LMAX + 1];               // K, with K[LMAX]=0 sentinel

    bool  m  = false;
    float kv = 0.0f;
    if (i < LMAX) {
        int j = (int)floorf((float)i / sstep);    // exact fp32 replication
        m = (i < L0) && (j < NPSI);
        int jc = min(max(j, 0), NPSI - 1);
        kv = m ? d_INT_PSI[jc] : 0.0f;
        shK[i] = kv;
    } else if (i == LMAX) {
        shK[LMAX] = 0.0f;
    }
    const int L = __syncthreads_count(m);         // mask is a prefix -> L taps

    // D[i] = K[i-1] - K[i] for i in [0, L]; zero-fill rest of DMAX
    if (i <= L) {
        float prev = (i == 0) ? 0.0f : shK[i - 1];
        d_D[bk][i] = prev - shK[i];
    } else if (i < DMAX) {
        d_D[bk][i] = 0.0f;
    }

    if (i == 0) {
        d_LD[bk]  = L + 1;
        d_OFF[bk] = (L - 2) / 2 + 1 - L;          // (off) - 1
        d_SQS[bk] = sqrtf(scale);
        // frequency_bands
        float center = 1.0f / (scale * tr[b]);
        float bw = bwp[k];
        float lo = fmaxf(0.008f, center * (1.0f - bw * 0.5f));
        float hi = fminf(0.12f,  center * (1.0f + bw * 0.5f));
        out_bands[bk * 2 + 0] = lo;
        out_bands[bk * 2 + 1] = hi;
    }
}

// ---------------------------------------------------------------------------
// Kernel 3: main FIR. One block per (b,r). 256 threads, each thread owns 5
// consecutive outputs with a register sliding window (stride-5 shared loads
// across lanes are coprime with 32 banks -> conflict-free).
// ---------------------------------------------------------------------------
__global__ void __launch_bounds__(256, 6)
k_cwt(const float* __restrict__ ts, float* __restrict__ out) {
    const int br = blockIdx.x;
    const int b  = br / REG;
    const int tid = threadIdx.x;

    __shared__ float shX[SHX];
    __shared__ float shD[DMAX];

    // zero-extended signal in shared
    for (int idx = tid; idx < SHX; idx += 256) shX[idx] = 0.0f;
    __syncthreads();
    const float* __restrict__ xrow = ts + (size_t)br * TLEN;
    for (int idx = tid; idx < TLEN; idx += 256) shX[XOFF + idx] = xrow[idx];
    __syncthreads();

    float* __restrict__ outbase = out + (size_t)br * NB * NOUT;

    for (int k = 0; k < NB; k++) {
        const int   bk  = b * NB + k;
        const int   LD  = d_LD[bk];
        const int   off = d_OFF[bk];
        const float sq  = d_SQS[bk];

        for (int idx = tid; idx < LD; idx += 256) shD[idx] = d_D[bk][idx];
        __syncthreads();

        if (tid < 240) {
            const float* __restrict__ p = shX + XOFF + 5 * tid + off;
            float a0 = 0.f, a1 = 0.f, a2 = 0.f, a3 = 0.f, a4 = 0.f;
            float w0 = p[0], w1 = p[1], w2 = p[2], w3 = p[3], w4 = p[4];
            #pragma unroll 5
            for (int i = 0; i < LD; i++) {
                const float d = shD[i];
                a0 = fmaf(w0, d, a0);
                a1 = fmaf(w1, d, a1);
                a2 = fmaf(w2, d, a2);
                a3 = fmaf(w3, d, a3);
                a4 = fmaf(w4, d, a4);
                w0 = w1; w1 = w2; w2 = w3; w3 = w4;
                w4 = p[i + 5];
            }
            float* __restrict__ o = outbase + (size_t)k * NOUT + 5 * tid;
            o[0] = sq * fabsf(a0);
            o[1] = sq * fabsf(a1);
            o[2] = sq * fabsf(a2);
            o[3] = sq * fabsf(a3);
            o[4] = sq * fabsf(a4);
        }
        __syncthreads();
    }
}

// ---------------------------------------------------------------------------
extern "C" void kernel_launch(void* const* d_in, const int* in_sizes, int n_in,
                              void* d_out, int out_size) {
    (void)in_sizes; (void)n_in; (void)out_size;
    const float* ts  = (const float*)d_in[0];
    const float* tr  = (const float*)d_in[1];
    const float* lsp = (const float*)d_in[2];
    const float* bwp = (const float*)d_in[3];
    float* out = (float*)d_out;

    float* bands = out + (size_t)BATCH * REG * NB * NOUT; // coeffs first, bands after

    k_init_psi<<<1, NPSI>>>();
    k_prep<<<BATCH * NB, DMAX>>>(tr, lsp, bwp, bands);
    k_cwt<<<BATCH * REG, 256>>>(ts, out);
}

// round 2
// speedup vs baseline: 1.0122x; 1.0122x over previous
#include <cuda_runtime.h>
#include <math.h>

// Problem constants (fixed shapes per setup_inputs)
#define BATCH 8
#define REG   400
#define TLEN  1200
#define NB    5
#define NPSI  1024
#define LMAX  544

#define NOUT  TLEN
#define XOFF  288                  // left zero pad in shared X (covers off >= -268)
#define SHX   1824
#define DMAX  576                  // padded taps per (b,k)
#define DH    288                  // DMAX/2 entries per phase

static __device__ float d_D[BATCH * NB][DMAX];
static __device__ int   d_LD[BATCH * NB];   // L + 1 taps
static __device__ int   d_OFF[BATCH * NB];  // off - 1
static __device__ float d_SQS[BATCH * NB];  // sqrt(scale)

// ---------------------------------------------------------------------------
// packed fp32x2 helpers
// ---------------------------------------------------------------------------
__device__ __forceinline__ void fma2(unsigned long long &a,
                                     unsigned long long x,
                                     unsigned long long d) {
    asm("fma.rn.f32x2 %0, %1, %2, %0;" : "+l"(a) : "l"(x), "l"(d));
}
__device__ __forceinline__ unsigned long long lds64(unsigned sa) {
    unsigned long long v;
    asm("ld.shared.b64 %0, [%1];" : "=l"(v) : "r"(sa));
    return v;
}
__device__ __forceinline__ void lds128(unsigned sa, unsigned long long &a,
                                       unsigned long long &b) {
    asm("ld.shared.v2.u64 {%0,%1}, [%2];" : "=l"(a), "=l"(b) : "r"(sa));
}

// ---------------------------------------------------------------------------
// Kernel 1 (fused): build INT_PSI (fp32 scan) + per-(b,k) prep + freq bands.
// One block per (b,k), 1024 threads.
// ---------------------------------------------------------------------------
__global__ void k_prep(const float* __restrict__ tr,
                       const float* __restrict__ lsp,
                       const float* __restrict__ bwp,
                       float* __restrict__ out_bands) {
    __shared__ float sp[NPSI];          // psi, then cumsum(psi)
    __shared__ float shK[LMAX + 1];

    const int bk = blockIdx.x;
    const int b  = bk / NB;
    const int k  = bk % NB;
    const int i  = threadIdx.x;

    const float STEP_F = (float)(16.0 / 1023.0);

    // psi
    {
        float x = -8.0f + STEP_F * (float)i;
        sp[i] = expf(-0.5f * x * x) * cosf(5.0f * x);
    }
    __syncthreads();
    // Hillis-Steele inclusive scan (fp32)
    for (int o = 1; o < NPSI; o <<= 1) {
        float add = (i >= o) ? sp[i - o] : 0.0f;
        __syncthreads();
        sp[i] += add;
        __syncthreads();
    }
    // sp[i]*STEP_F == INT_PSI[i]

    const float trf   = tr[b] / 2.0f;
    const float scale = expf(lsp[k]) / trf;
    const float sstep = scale * STEP_F;
    const int   L0    = (int)floorf(scale * 16.0f) + 2;

    bool m = false;
    if (i < LMAX) {
        int j = (int)floorf((float)i / sstep);
        m = (i < L0) && (j < NPSI);
        int jc = min(max(j, 0), NPSI - 1);
        shK[i] = m ? sp[jc] * STEP_F : 0.0f;
    } else if (i == LMAX) {
        shK[LMAX] = 0.0f;
    }
    const int L = __syncthreads_count(m);   // mask is a prefix

    if (i <= L) {
        float prev = (i == 0) ? 0.0f : shK[i - 1];
        d_D[bk][i] = prev - shK[i];
    } else if (i < DMAX) {
        d_D[bk][i] = 0.0f;
    }

    if (i == 0) {
        d_LD[bk]  = L + 1;
        d_OFF[bk] = (L - 2) / 2 + 1 - L;
        d_SQS[bk] = sqrtf(scale);
        float center = 1.0f / (scale * tr[b]);
        float bw = bwp[k];
        out_bands[bk * 2 + 0] = fmaxf(0.008f, center * (1.0f - bw * 0.5f));
        out_bands[bk * 2 + 1] = fminf(0.12f,  center * (1.0f + bw * 0.5f));
    }
}

// ---------------------------------------------------------------------------
// Kernel 2: main FIR with packed fma.rn.f32x2.
// One block per (b,r). 128 threads; threads 0..119 each own 10 outputs as
// 5 packed accumulators. Taps split into even/odd phase passes so packed
// X-window pairs shift cleanly; second X copy shifted by 1 element keeps
// the odd-parity pairs 8B-aligned.
// ---------------------------------------------------------------------------
__global__ void __launch_bounds__(128, 8)
k_cwt(const float* __restrict__ ts, float* __restrict__ out) {
    const int br  = blockIdx.x;
    const int b   = br / REG;
    const int tid = threadIdx.x;

    __shared__ __align__(16) float  shXA[SHX];
    __shared__ __align__(16) float  shXB[SHX + 2];
    __shared__ __align__(16) float2 shDE[DH];
    __shared__ __align__(16) float2 shDO[DH];

    for (int idx = tid; idx < SHX; idx += 128) shXA[idx] = 0.0f;
    for (int idx = tid; idx < SHX + 2; idx += 128) shXB[idx] = 0.0f;
    __syncthreads();
    const float* __restrict__ xrow = ts + (size_t)br * TLEN;
    for (int idx = tid; idx < TLEN; idx += 128) {
        float v = xrow[idx];
        shXA[XOFF + idx]     = v;
        shXB[XOFF + idx + 1] = v;   // shXB[m] = Xext[m-1]
    }
    __syncthreads();

    float* __restrict__ outbase = out + (size_t)br * NB * NOUT;

    const unsigned aXA = (unsigned)__cvta_generic_to_shared(shXA);
    const unsigned aXB = (unsigned)__cvta_generic_to_shared(shXB);
    const unsigned aDE = (unsigned)__cvta_generic_to_shared(shDE);
    const unsigned aDO = (unsigned)__cvta_generic_to_shared(shDO);

    for (int k = 0; k < NB; k++) {
        const int   bk  = b * NB + k;
        const int   LD  = d_LD[bk];
        const int   off = d_OFF[bk];
        const float sq  = d_SQS[bk];

        // stage duplicated per-phase tap arrays: shDE[ii]=(D[2ii],D[2ii]), etc.
        for (int idx = tid; idx < DH; idx += 128) {
            float e = d_D[bk][2 * idx];
            float o = d_D[bk][2 * idx + 1];
            shDE[idx] = make_float2(e, e);
            shDO[idx] = make_float2(o, o);
        }
        __syncthreads();

        if (tid < 120) {
            const int s = XOFF + off + 10 * tid;   // base element index in Xext
            unsigned long long A0 = 0, A1 = 0, A2 = 0, A3 = 0, A4 = 0;
            const int S = (LD + 1) >> 1;           // steps per phase (zero-padded)

            #pragma unroll
            for (int phi = 0; phi < 2; phi++) {
                // pair (m, m+1) of Xext, m = s+phi+2*(ii+p):
                //   m even -> shXA[m];  m odd -> shXB[m+1]  (both 8B-aligned)
                const int  m0   = s + phi;
                const bool even = ((m0 & 1) == 0);
                const unsigned pA = even ? (aXA + 4u * (unsigned)m0)
                                         : (aXB + 4u * (unsigned)(m0 + 1));
                const unsigned dA = phi ? aDO : aDE;

                unsigned long long P0 = lds64(pA + 0);
                unsigned long long P1 = lds64(pA + 8);
                unsigned long long P2 = lds64(pA + 16);
                unsigned long long P3 = lds64(pA + 24);
                unsigned long long P4 = lds64(pA + 32);
                unsigned long long P5 = lds64(pA + 40);

                int ii = 0;
                #pragma unroll 2
                for (; ii + 2 <= S; ii += 2) {
                    unsigned long long dd0, dd1;
                    lds128(dA + 8u * (unsigned)ii, dd0, dd1);
                    // step ii: pairs P0..P4
                    fma2(A0, P0, dd0); fma2(A1, P1, dd0);
                    fma2(A2, P2, dd0); fma2(A3, P3, dd0);
                    fma2(A4, P4, dd0);
                    unsigned long long P6 = lds64(pA + 8u * (unsigned)(ii + 6));
                    // step ii+1: pairs P1..P5
                    fma2(A0, P1, dd1); fma2(A1, P2, dd1);
                    fma2(A2, P3, dd1); fma2(A3, P4, dd1);
                    fma2(A4, P5, dd1);
                    unsigned long long P7 = lds64(pA + 8u * (unsigned)(ii + 7));
                    P0 = P2; P1 = P3; P2 = P4; P3 = P5; P4 = P6; P5 = P7;
                }
                if (ii < S) {
                    unsigned long long dd0 = lds64(dA + 8u * (unsigned)ii);
                    fma2(A0, P0, dd0); fma2(A1, P1, dd0);
                    fma2(A2, P2, dd0); fma2(A3, P3, dd0);
                    fma2(A4, P4, dd0);
                }
            }

            // epilogue: scale * abs, packed stores
            float2* __restrict__ o2 =
                (float2*)(outbase + (size_t)k * NOUT + 10 * tid);
            float2 r;
            float2 v;
            v = *(float2*)&A0; r.x = sq * fabsf(v.x); r.y = sq * fabsf(v.y); o2[0] = r;
            v = *(float2*)&A1; r.x = sq * fabsf(v.x); r.y = sq * fabsf(v.y); o2[1] = r;
            v = *(float2*)&A2; r.x = sq * fabsf(v.x); r.y = sq * fabsf(v.y); o2[2] = r;
            v = *(float2*)&A3; r.x = sq * fabsf(v.x); r.y = sq * fabsf(v.y); o2[3] = r;
            v = *(float2*)&A4; r.x = sq * fabsf(v.x); r.y = sq * fabsf(v.y); o2[4] = r;
        }
        __syncthreads();
    }
}

// ---------------------------------------------------------------------------
extern "C" void kernel_launch(void* const* d_in, const int* in_sizes, int n_in,
                              void* d_out, int out_size) {
    (void)in_sizes; (void)n_in; (void)out_size;
    const float* ts  = (const float*)d_in[0];
    const float* tr  = (const float*)d_in[1];
    const float* lsp = (const float*)d_in[2];
    const float* bwp = (const float*)d_in[3];
    float* out = (float*)d_out;

    float* bands = out + (size_t)BATCH * REG * NB * NOUT;

    k_prep<<<BATCH * NB, NPSI>>>(tr, lsp, bwp, bands);
    k_cwt<<<BATCH * REG, 128>>>(ts, out);
}

// round 3
// speedup vs baseline: 1.3720x; 1.3555x over previous
#include <cuda_runtime.h>
#include <math.h>

#define BATCH 8
#define REG   400
#define TLEN  1200
#define NB    5
#define NPSI  1024
#define LMAX  544

#define NOUT  TLEN
#define XOFF  288                  // left zero pad in shared X
#define SHX   1856
#define DMAX  576                  // padded taps per (b,k)
#define DH    288                  // per-phase duplicated tap pairs

static __device__ float d_D[BATCH * NB][DMAX];
static __device__ int   d_LD[BATCH * NB];   // L + 1 taps
static __device__ int   d_OFF[BATCH * NB];  // off - 1
static __device__ float d_SQS[BATCH * NB];  // sqrt(scale)

// ---------------------------------------------------------------------------
// packed fp32x2 helpers
// ---------------------------------------------------------------------------
__device__ __forceinline__ void fma2(unsigned long long &a,
                                     unsigned long long x,
                                     unsigned long long d) {
    asm("fma.rn.f32x2 %0, %1, %2, %0;" : "+l"(a) : "l"(x), "l"(d));
}
__device__ __forceinline__ unsigned long long lds64(unsigned sa) {
    unsigned long long v;
    asm("ld.shared.b64 %0, [%1];" : "=l"(v) : "r"(sa));
    return v;
}
__device__ __forceinline__ void lds128(unsigned sa, unsigned long long &a,
                                       unsigned long long &b) {
    asm("ld.shared.v2.u64 {%0,%1}, [%2];" : "=l"(a), "=l"(b) : "r"(sa));
}

// ---------------------------------------------------------------------------
// Kernel 1: INT_PSI (fp32 scan) + per-(b,k) taps + freq bands.
// ---------------------------------------------------------------------------
__global__ void k_prep(const float* __restrict__ tr,
                       const float* __restrict__ lsp,
                       const float* __restrict__ bwp,
                       float* __restrict__ out_bands) {
    __shared__ float sp[NPSI];
    __shared__ float shK[LMAX + 1];

    const int bk = blockIdx.x;
    const int b  = bk / NB;
    const int k  = bk % NB;
    const int i  = threadIdx.x;

    const float STEP_F = (float)(16.0 / 1023.0);

    {
        float x = -8.0f + STEP_F * (float)i;
        sp[i] = expf(-0.5f * x * x) * cosf(5.0f * x);
    }
    __syncthreads();
    for (int o = 1; o < NPSI; o <<= 1) {
        float add = (i >= o) ? sp[i - o] : 0.0f;
        __syncthreads();
        sp[i] += add;
        __syncthreads();
    }

    const float trf   = tr[b] / 2.0f;
    const float scale = expf(lsp[k]) / trf;
    const float sstep = scale * STEP_F;
    const int   L0    = (int)floorf(scale * 16.0f) + 2;

    bool m = false;
    if (i < LMAX) {
        int j = (int)floorf((float)i / sstep);
        m = (i < L0) && (j < NPSI);
        int jc = min(max(j, 0), NPSI - 1);
        shK[i] = m ? sp[jc] * STEP_F : 0.0f;
    } else if (i == LMAX) {
        shK[LMAX] = 0.0f;
    }
    const int L = __syncthreads_count(m);

    if (i <= L) {
        float prev = (i == 0) ? 0.0f : shK[i - 1];
        d_D[bk][i] = prev - shK[i];
    } else if (i < DMAX) {
        d_D[bk][i] = 0.0f;
    }

    if (i == 0) {
        d_LD[bk]  = L + 1;
        d_OFF[bk] = (L - 2) / 2 + 1 - L;
        d_SQS[bk] = sqrtf(scale);
        float center = 1.0f / (scale * tr[b]);
        float bw = bwp[k];
        out_bands[bk * 2 + 0] = fmaxf(0.008f, center * (1.0f - bw * 0.5f));
        out_bands[bk * 2 + 1] = fminf(0.12f,  center * (1.0f + bw * 0.5f));
    }
}

// ---------------------------------------------------------------------------
// Kernel 2: FIR, packed f32x2, MOV-free 6-step rotated window.
// One block per (b,r); threads 0..119 own 10 outputs (5 packed accumulators).
// Step count per phase rounded UP to a multiple of 6 with zero taps.
// ---------------------------------------------------------------------------
__global__ void __launch_bounds__(128, 8)
k_cwt(const float* __restrict__ ts, float* __restrict__ out) {
    const int br  = blockIdx.x;
    const int b   = br / REG;
    const int tid = threadIdx.x;

    __shared__ __align__(16) float  shXA[SHX];
    __shared__ __align__(16) float  shXB[SHX + 2];
    __shared__ __align__(16) float2 shDE[DH];
    __shared__ __align__(16) float2 shDO[DH];

    for (int idx = tid; idx < SHX; idx += 128) shXA[idx] = 0.0f;
    for (int idx = tid; idx < SHX + 2; idx += 128) shXB[idx] = 0.0f;
    __syncthreads();
    const float* __restrict__ xrow = ts + (size_t)br * TLEN;
    for (int idx = tid; idx < TLEN; idx += 128) {
        float v = xrow[idx];
        shXA[XOFF + idx]     = v;
        shXB[XOFF + idx + 1] = v;      // shXB[m] = Xext[m-1]
    }
    __syncthreads();

    float* __restrict__ outbase = out + (size_t)br * NB * NOUT;

    const unsigned aXA = (unsigned)__cvta_generic_to_shared(shXA);
    const unsigned aXB = (unsigned)__cvta_generic_to_shared(shXB);
    const unsigned aDE = (unsigned)__cvta_generic_to_shared(shDE);
    const unsigned aDO = (unsigned)__cvta_generic_to_shared(shDO);

    for (int k = 0; k < NB; k++) {
        const int   bk  = b * NB + k;
        const int   LD  = d_LD[bk];
        const int   off = d_OFF[bk];
        const float sq  = d_SQS[bk];

        // stage FULL duplicated per-phase tap arrays (zero-padded taps included)
        {
            const float2* __restrict__ dsrc = (const float2*)d_D[bk];
            for (int idx = tid; idx < DH; idx += 128) {
                float2 de = dsrc[idx];
                shDE[idx] = make_float2(de.x, de.x);
                shDO[idx] = make_float2(de.y, de.y);
            }
        }
        __syncthreads();

        if (tid < 120) {
            const int s = XOFF + off + 10 * tid;
            unsigned long long A0 = 0, A1 = 0, A2 = 0, A3 = 0, A4 = 0;
            const int S  = (LD + 1) >> 1;
            const int S6 = ((S + 5) / 6) * 6;     // zero-tap padded, no remainder

            #pragma unroll
            for (int phi = 0; phi < 2; phi++) {
                const int  m0   = s + phi;
                const bool even = ((m0 & 1) == 0);
                unsigned pX = even ? (aXA + 4u * (unsigned)m0)
                                   : (aXB + 4u * (unsigned)(m0 + 1));
                unsigned pD = phi ? aDO : aDE;

                unsigned long long W0 = lds64(pX + 0);
                unsigned long long W1 = lds64(pX + 8);
                unsigned long long W2 = lds64(pX + 16);
                unsigned long long W3 = lds64(pX + 24);
                unsigned long long W4 = lds64(pX + 32);
                unsigned long long W5 = lds64(pX + 40);

                #pragma unroll 2
                for (int it = 0; it < S6; it += 6) {
                    unsigned long long d0, d1, d2, d3, d4, d5;
                    lds128(pD, d0, d1);
                    lds128(pD + 16, d2, d3);
                    lds128(pD + 32, d4, d5);
                    // step 0: pairs q..q+4
                    fma2(A0, W0, d0); fma2(A1, W1, d0); fma2(A2, W2, d0);
                    fma2(A3, W3, d0); fma2(A4, W4, d0);
                    W0 = lds64(pX + 48);
                    // step 1
                    fma2(A0, W1, d1); fma2(A1, W2, d1); fma2(A2, W3, d1);
                    fma2(A3, W4, d1); fma2(A4, W5, d1);
                    W1 = lds64(pX + 56);
                    // step 2
                    fma2(A0, W2, d2); fma2(A1, W3, d2); fma2(A2, W4, d2);
                    fma2(A3, W5, d2); fma2(A4, W0, d2);
                    W2 = lds64(pX + 64);
                    // step 3
                    fma2(A0, W3, d3); fma2(A1, W4, d3); fma2(A2, W5, d3);
                    fma2(A3, W0, d3); fma2(A4, W1, d3);
                    W3 = lds64(pX + 72);
                    // step 4
                    fma2(A0, W4, d4); fma2(A1, W5, d4); fma2(A2, W0, d4);
                    fma2(A3, W1, d4); fma2(A4, W2, d4);
                    W4 = lds64(pX + 80);
                    // step 5
                    fma2(A0, W5, d5); fma2(A1, W0, d5); fma2(A2, W1, d5);
                    fma2(A3, W2, d5); fma2(A4, W3, d5);
                    W5 = lds64(pX + 88);

                    pX += 48;
                    pD += 48;
                }
            }

            float2* __restrict__ o2 =
                (float2*)(outbase + (size_t)k * NOUT + 10 * tid);
            float2 r, v;
            v = *(float2*)&A0; r.x = sq * fabsf(v.x); r.y = sq * fabsf(v.y); o2[0] = r;
            v = *(float2*)&A1; r.x = sq * fabsf(v.x); r.y = sq * fabsf(v.y); o2[1] = r;
            v = *(float2*)&A2; r.x = sq * fabsf(v.x); r.y = sq * fabsf(v.y); o2[2] = r;
            v = *(float2*)&A3; r.x = sq * fabsf(v.x); r.y = sq * fabsf(v.y); o2[3] = r;
            v = *(float2*)&A4; r.x = sq * fabsf(v.x); r.y = sq * fabsf(v.y); o2[4] = r;
        }
        __syncthreads();
    }
}

// ---------------------------------------------------------------------------
extern "C" void kernel_launch(void* const* d_in, const int* in_sizes, int n_in,
                              void* d_out, int out_size) {
    (void)in_sizes; (void)n_in; (void)out_size;
    const float* ts  = (const float*)d_in[0];
    const float* tr  = (const float*)d_in[1];
    const float* lsp = (const float*)d_in[2];
    const float* bwp = (const float*)d_in[3];
    float* out = (float*)d_out;

    float* bands = out + (size_t)BATCH * REG * NB * NOUT;

    k_prep<<<BATCH * NB, NPSI>>>(tr, lsp, bwp, bands);
    k_cwt<<<BATCH * REG, 128>>>(ts, out);
}

// round 4
// speedup vs baseline: 1.3736x; 1.0012x over previous
#include <cuda_runtime.h>
#include <math.h>

#define BATCH 8
#define REG   400
#define TLEN  1200
#define NB    5
#define NPSI  1024
#define LMAX  544

#define NOUT  TLEN
#define XOFF  288                  // left zero pad in shared X
#define SHX   1856
#define DMAX  576                  // padded taps per (b,k)
#define DH    288                  // tap pairs

static __device__ float d_D[BATCH * NB][DMAX];
static __device__ int   d_LD[BATCH * NB];   // L + 1 taps
static __device__ int   d_OFF[BATCH * NB];  // off - 1
static __device__ float d_SQS[BATCH * NB];  // sqrt(scale)

// ---------------------------------------------------------------------------
// packed fp32x2 helpers
// ---------------------------------------------------------------------------
__device__ __forceinline__ void fma2(unsigned long long &a,
                                     unsigned long long x,
                                     unsigned long long d) {
    asm("fma.rn.f32x2 %0, %1, %2, %0;" : "+l"(a) : "l"(x), "l"(d));
}
__device__ __forceinline__ unsigned long long lds64(unsigned sa) {
    unsigned long long v;
    asm("ld.shared.b64 %0, [%1];" : "=l"(v) : "r"(sa));
    return v;
}
__device__ __forceinline__ void lds128(unsigned sa, unsigned long long &a,
                                       unsigned long long &b) {
    asm("ld.shared.v2.u64 {%0,%1}, [%2];" : "=l"(a), "=l"(b) : "r"(sa));
}

// ---------------------------------------------------------------------------
// Kernel 1: INT_PSI (fp32 scan) + per-(b,k) taps + freq bands.
// ---------------------------------------------------------------------------
__global__ void k_prep(const float* __restrict__ tr,
                       const float* __restrict__ lsp,
                       const float* __restrict__ bwp,
                       float* __restrict__ out_bands) {
    __shared__ float sp[NPSI];
    __shared__ float shK[LMAX + 1];

    const int bk = blockIdx.x;
    const int b  = bk / NB;
    const int k  = bk % NB;
    const int i  = threadIdx.x;

    const float STEP_F = (float)(16.0 / 1023.0);

    {
        float x = -8.0f + STEP_F * (float)i;
        sp[i] = expf(-0.5f * x * x) * cosf(5.0f * x);
    }
    __syncthreads();
    for (int o = 1; o < NPSI; o <<= 1) {
        float add = (i >= o) ? sp[i - o] : 0.0f;
        __syncthreads();
        sp[i] += add;
        __syncthreads();
    }

    const float trf   = tr[b] / 2.0f;
    const float scale = expf(lsp[k]) / trf;
    const float sstep = scale * STEP_F;
    const int   L0    = (int)floorf(scale * 16.0f) + 2;

    bool m = false;
    if (i < LMAX) {
        int j = (int)floorf((float)i / sstep);
        m = (i < L0) && (j < NPSI);
        int jc = min(max(j, 0), NPSI - 1);
        shK[i] = m ? sp[jc] * STEP_F : 0.0f;
    } else if (i == LMAX) {
        shK[LMAX] = 0.0f;
    }
    const int L = __syncthreads_count(m);

    if (i <= L) {
        float prev = (i == 0) ? 0.0f : shK[i - 1];
        d_D[bk][i] = prev - shK[i];
    } else if (i < DMAX) {
        d_D[bk][i] = 0.0f;
    }

    if (i == 0) {
        d_LD[bk]  = L + 1;
        d_OFF[bk] = (L - 2) / 2 + 1 - L;
        d_SQS[bk] = sqrtf(scale);
        float center = 1.0f / (scale * tr[b]);
        float bw = bwp[k];
        out_bands[bk * 2 + 0] = fmaxf(0.008f, center * (1.0f - bw * 0.5f));
        out_bands[bk * 2 + 1] = fminf(0.12f,  center * (1.0f + bw * 0.5f));
    }
}

// ---------------------------------------------------------------------------
// Kernel 2: FIR, packed f32x2, polyphase-fused even/odd taps.
//   E[n] = sum_ii X[n+2ii] * D[2ii]
//   V[n] = sum_ii X[n+2ii] * D[2ii+1]
//   y[n] = E[n] + V[n+1]           (shift resolved in the epilogue)
// One pass over the tap pairs: 1 X pair load + 1 D quad load feed 11 FFMA2.
// Thread t owns outputs 10t..10t+9: E0..E4 pairs + V0..V5 pairs.
// ---------------------------------------------------------------------------
__global__ void __launch_bounds__(128, 8)
k_cwt(const float* __restrict__ ts, float* __restrict__ out) {
    const int br  = blockIdx.x;
    const int b   = br / REG;
    const int tid = threadIdx.x;

    __shared__ __align__(16) float  shXA[SHX];
    __shared__ __align__(16) float  shXB[SHX + 2];
    __shared__ __align__(16) float4 shD4[DH];   // (De,De,Do,Do) per tap pair

    for (int idx = tid; idx < SHX; idx += 128) shXA[idx] = 0.0f;
    for (int idx = tid; idx < SHX + 2; idx += 128) shXB[idx] = 0.0f;
    __syncthreads();
    const float* __restrict__ xrow = ts + (size_t)br * TLEN;
    for (int idx = tid; idx < TLEN; idx += 128) {
        float v = xrow[idx];
        shXA[XOFF + idx]     = v;
        shXB[XOFF + idx + 1] = v;      // shXB[m] = Xext[m-1]
    }
    __syncthreads();

    float* __restrict__ outbase = out + (size_t)br * NB * NOUT;

    const unsigned aXA = (unsigned)__cvta_generic_to_shared(shXA);
    const unsigned aXB = (unsigned)__cvta_generic_to_shared(shXB);
    const unsigned aD4 = (unsigned)__cvta_generic_to_shared(shD4);

    for (int k = 0; k < NB; k++) {
        const int   bk  = b * NB + k;
        const int   LD  = d_LD[bk];
        const int   off = d_OFF[bk];
        const float sq  = d_SQS[bk];

        // stage (De,De,Do,Do) quads, zero-padded taps included
        {
            const float2* __restrict__ dsrc = (const float2*)d_D[bk];
            for (int idx = tid; idx < DH; idx += 128) {
                float2 p = dsrc[idx];
                shD4[idx] = make_float4(p.x, p.x, p.y, p.y);
            }
        }
        __syncthreads();

        if (tid < 120) {
            const int  m0   = XOFF + off + 10 * tid;   // even-window base elem
            const bool even = ((m0 & 1) == 0);
            unsigned pX = even ? (aXA + 4u * (unsigned)m0)
                               : (aXB + 4u * (unsigned)(m0 + 1));
            unsigned pD = aD4;

            const int S  = (LD + 1) >> 1;              // tap pairs
            const int S6 = ((S + 5) / 6) * 6;          // zero-tap padded

            unsigned long long E0 = 0, E1 = 0, E2 = 0, E3 = 0, E4 = 0;
            unsigned long long V0 = 0, V1 = 0, V2 = 0, V3 = 0, V4 = 0, V5 = 0;

            unsigned long long W0 = lds64(pX + 0);
            unsigned long long W1 = lds64(pX + 8);
            unsigned long long W2 = lds64(pX + 16);
            unsigned long long W3 = lds64(pX + 24);
            unsigned long long W4 = lds64(pX + 32);
            unsigned long long W5 = lds64(pX + 40);

#define STEP(Q0, Q1, Q2, Q3, Q4, Q5, R) do {                                \
            unsigned long long de_, do_;                                    \
            lds128(pD + 16u * (R), de_, do_);                               \
            fma2(E0, Q0, de_); fma2(V0, Q0, do_);                           \
            fma2(E1, Q1, de_); fma2(V1, Q1, do_);                           \
            fma2(E2, Q2, de_); fma2(V2, Q2, do_);                           \
            fma2(E3, Q3, de_); fma2(V3, Q3, do_);                           \
            fma2(E4, Q4, de_); fma2(V4, Q4, do_);                           \
            fma2(V5, Q5, do_);                                              \
            Q0 = lds64(pX + 8u * ((R) + 6));                                \
        } while (0)

            for (int it = 0; it < S6; it += 6) {
                STEP(W0, W1, W2, W3, W4, W5, 0);
                STEP(W1, W2, W3, W4, W5, W0, 1);
                STEP(W2, W3, W4, W5, W0, W1, 2);
                STEP(W3, W4, W5, W0, W1, W2, 3);
                STEP(W4, W5, W0, W1, W2, W3, 4);
                STEP(W5, W0, W1, W2, W3, W4, 5);
                pX += 48;
                pD += 96;
            }
#undef STEP

            // epilogue: y[2j] = E_j.lo + V_j.hi ; y[2j+1] = E_j.hi + V_{j+1}.lo
            float2* __restrict__ o2 =
                (float2*)(outbase + (size_t)k * NOUT + 10 * tid);
            {
                float2 e, va, vb, r;
                e = *(float2*)&E0; va = *(float2*)&V0; vb = *(float2*)&V1;
                r.x = sq * fabsf(e.x + va.y); r.y = sq * fabsf(e.y + vb.x); o2[0] = r;
                e = *(float2*)&E1; va = vb; vb = *(float2*)&V2;
                r.x = sq * fabsf(e.x + va.y); r.y = sq * fabsf(e.y + vb.x); o2[1] = r;
                e = *(float2*)&E2; va = vb; vb = *(float2*)&V3;
                r.x = sq * fabsf(e.x + va.y); r.y = sq * fabsf(e.y + vb.x); o2[2] = r;
                e = *(float2*)&E3; va = vb; vb = *(float2*)&V4;
                r.x = sq * fabsf(e.x + va.y); r.y = sq * fabsf(e.y + vb.x); o2[3] = r;
                e = *(float2*)&E4; va = vb; vb = *(float2*)&V5;
                r.x = sq * fabsf(e.x + va.y); r.y = sq * fabsf(e.y + vb.x); o2[4] = r;
            }
        }
        __syncthreads();
    }
}

// ---------------------------------------------------------------------------
extern "C" void kernel_launch(void* const* d_in, const int* in_sizes, int n_in,
                              void* d_out, int out_size) {
    (void)in_sizes; (void)n_in; (void)out_size;
    const float* ts  = (const float*)d_in[0];
    const float* tr  = (const float*)d_in[1];
    const float* lsp = (const float*)d_in[2];
    const float* bwp = (const float*)d_in[3];
    float* out = (float*)d_out;

    float* bands = out + (size_t)BATCH * REG * NB * NOUT;

    k_prep<<<BATCH * NB, NPSI>>>(tr, lsp, bwp, bands);
    k_cwt<<<BATCH * REG, 128>>>(ts, out);
}

// round 5
// speedup vs baseline: 1.4319x; 1.0424x over previous
#include <cuda_runtime.h>
#include <math.h>

#define BATCH 8
#define REG   400
#define TLEN  1200
#define NB    5
#define NPSI  1024
#define LMAX  544

#define NOUT  TLEN
#define XOFF  288                  // left zero pad in shared X
#define SHX   1856
#define DMAX  576                  // padded taps per (b,k)
#define DH    288                  // tap pairs

static __device__ float d_D[BATCH * NB][DMAX];
static __device__ int   d_LD[BATCH * NB];   // L + 1 taps
static __device__ int   d_OFF[BATCH * NB];  // off - 1
static __device__ float d_SQS[BATCH * NB];  // sqrt(scale)

// ---------------------------------------------------------------------------
// packed fp32x2 helpers
// ---------------------------------------------------------------------------
__device__ __forceinline__ void fma2(unsigned long long &a,
                                     unsigned long long x,
                                     unsigned long long d) {
    asm("fma.rn.f32x2 %0, %1, %2, %0;" : "+l"(a) : "l"(x), "l"(d));
}
__device__ __forceinline__ unsigned long long lds64(unsigned sa) {
    unsigned long long v;
    asm("ld.shared.b64 %0, [%1];" : "=l"(v) : "r"(sa));
    return v;
}
__device__ __forceinline__ void lds128(unsigned sa, unsigned long long &a,
                                       unsigned long long &b) {
    asm("ld.shared.v2.u64 {%0,%1}, [%2];" : "=l"(a), "=l"(b) : "r"(sa));
}

// ---------------------------------------------------------------------------
// Kernel 1: INT_PSI (fp32 scan) + per-(b,k) taps + freq bands.
// ---------------------------------------------------------------------------
__global__ void k_prep(const float* __restrict__ tr,
                       const float* __restrict__ lsp,
                       const float* __restrict__ bwp,
                       float* __restrict__ out_bands) {
    __shared__ float sp[NPSI];
    __shared__ float shK[LMAX + 1];

    const int bk = blockIdx.x;
    const int b  = bk / NB;
    const int k  = bk % NB;
    const int i  = threadIdx.x;

    const float STEP_F = (float)(16.0 / 1023.0);

    {
        float x = -8.0f + STEP_F * (float)i;
        sp[i] = expf(-0.5f * x * x) * cosf(5.0f * x);
    }
    __syncthreads();
    for (int o = 1; o < NPSI; o <<= 1) {
        float add = (i >= o) ? sp[i - o] : 0.0f;
        __syncthreads();
        sp[i] += add;
        __syncthreads();
    }

    const float trf   = tr[b] / 2.0f;
    const float scale = expf(lsp[k]) / trf;
    const float sstep = scale * STEP_F;
    const int   L0    = (int)floorf(scale * 16.0f) + 2;

    bool m = false;
    if (i < LMAX) {
        int j = (int)floorf((float)i / sstep);
        m = (i < L0) && (j < NPSI);
        int jc = min(max(j, 0), NPSI - 1);
        shK[i] = m ? sp[jc] * STEP_F : 0.0f;
    } else if (i == LMAX) {
        shK[LMAX] = 0.0f;
    }
    const int L = __syncthreads_count(m);

    if (i <= L) {
        float prev = (i == 0) ? 0.0f : shK[i - 1];
        d_D[bk][i] = prev - shK[i];
    } else if (i < DMAX) {
        d_D[bk][i] = 0.0f;
    }

    if (i == 0) {
        d_LD[bk]  = L + 1;
        d_OFF[bk] = (L - 2) / 2 + 1 - L;
        d_SQS[bk] = sqrtf(scale);
        float center = 1.0f / (scale * tr[b]);
        float bw = bwp[k];
        out_bands[bk * 2 + 0] = fmaxf(0.008f, center * (1.0f - bw * 0.5f));
        out_bands[bk * 2 + 1] = fminf(0.12f,  center * (1.0f + bw * 0.5f));
    }
}

// ---------------------------------------------------------------------------
// Kernel 2: FIR, packed f32x2, polyphase-fused, 10 FFMA2 per step.
//   y[n] = E[n] + V[n+1];  the boundary V[10t+10] is thread (t+1)'s V0.lo,
//   exchanged through shV at the existing end-of-band barrier.
// All 128 threads compute (t=120..127 only feed the exchange); threads
// 0..119 store 10 outputs each.
// ---------------------------------------------------------------------------
__global__ void __launch_bounds__(128, 8)
k_cwt(const float* __restrict__ ts, float* __restrict__ out) {
    const int br  = blockIdx.x;
    const int b   = br / REG;
    const int tid = threadIdx.x;

    __shared__ __align__(16) float  shXA[SHX];
    __shared__ __align__(16) float  shXB[SHX + 2];
    __shared__ __align__(16) float4 shD4[DH];   // (De,De,Do,Do) per tap pair
    __shared__ float shV[129];

    for (int idx = tid; idx < SHX; idx += 128) shXA[idx] = 0.0f;
    for (int idx = tid; idx < SHX + 2; idx += 128) shXB[idx] = 0.0f;
    __syncthreads();
    const float* __restrict__ xrow = ts + (size_t)br * TLEN;
    for (int idx = tid; idx < TLEN; idx += 128) {
        float v = xrow[idx];
        shXA[XOFF + idx]     = v;
        shXB[XOFF + idx + 1] = v;      // shXB[m] = Xext[m-1]
    }
    // stage band 0's taps
    {
        const float2* __restrict__ dsrc = (const float2*)d_D[b * NB];
        for (int idx = tid; idx < DH; idx += 128) {
            float2 p = dsrc[idx];
            shD4[idx] = make_float4(p.x, p.x, p.y, p.y);
        }
    }
    __syncthreads();

    float* __restrict__ outbase = out + (size_t)br * NB * NOUT;

    const unsigned aXA = (unsigned)__cvta_generic_to_shared(shXA);
    const unsigned aXB = (unsigned)__cvta_generic_to_shared(shXB);
    const unsigned aD4 = (unsigned)__cvta_generic_to_shared(shD4);

    for (int k = 0; k < NB; k++) {
        const int   bk  = b * NB + k;
        const int   LD  = d_LD[bk];
        const int   off = d_OFF[bk];
        const float sq  = d_SQS[bk];

        const int  m0   = XOFF + off + 10 * tid;   // even-window base elem
        const bool even = ((m0 & 1) == 0);
        unsigned pX = even ? (aXA + 4u * (unsigned)m0)
                           : (aXB + 4u * (unsigned)(m0 + 1));
        unsigned pD = aD4;

        const int S  = (LD + 1) >> 1;              // tap pairs
        const int S6 = ((S + 5) / 6) * 6;          // zero-tap padded

        unsigned long long E0 = 0, E1 = 0, E2 = 0, E3 = 0, E4 = 0;
        unsigned long long V0 = 0, V1 = 0, V2 = 0, V3 = 0, V4 = 0;

        unsigned long long W0 = lds64(pX + 0);
        unsigned long long W1 = lds64(pX + 8);
        unsigned long long W2 = lds64(pX + 16);
        unsigned long long W3 = lds64(pX + 24);
        unsigned long long W4 = lds64(pX + 32);
        unsigned long long W5 = lds64(pX + 40);

#define STEP(Q0, Q1, Q2, Q3, Q4, R) do {                                \
        unsigned long long de_, do_;                                    \
        lds128(pD + 16u * (R), de_, do_);                               \
        fma2(E0, Q0, de_); fma2(V0, Q0, do_);                           \
        fma2(E1, Q1, de_); fma2(V1, Q1, do_);                           \
        fma2(E2, Q2, de_); fma2(V2, Q2, do_);                           \
        fma2(E3, Q3, de_); fma2(V3, Q3, do_);                           \
        fma2(E4, Q4, de_); fma2(V4, Q4, do_);                           \
        Q0 = lds64(pX + 8u * ((R) + 6));                                \
    } while (0)

        #pragma unroll 2
        for (int it = 0; it < S6; it += 6) {
            STEP(W0, W1, W2, W3, W4, 0);
            STEP(W1, W2, W3, W4, W5, 1);
            STEP(W2, W3, W4, W5, W0, 2);
            STEP(W3, W4, W5, W0, W1, 3);
            STEP(W4, W5, W0, W1, W2, 4);
            STEP(W5, W0, W1, W2, W3, 5);
            pX += 48;
            pD += 96;
        }
#undef STEP

        // exchange V0.lo with neighbor thread
        shV[tid] = ((float2*)&V0)->x;
        __syncthreads();

        if (tid < 120) {
            const float vlast = shV[tid + 1];   // V[10t+10]
            float2* __restrict__ o2 =
                (float2*)(outbase + (size_t)k * NOUT + 10 * tid);
            float2 e, va, vb, r;
            e = *(float2*)&E0; va = *(float2*)&V0; vb = *(float2*)&V1;
            r.x = sq * fabsf(e.x + va.y); r.y = sq * fabsf(e.y + vb.x); o2[0] = r;
            e = *(float2*)&E1; va = vb; vb = *(float2*)&V2;
            r.x = sq * fabsf(e.x + va.y); r.y = sq * fabsf(e.y + vb.x); o2[1] = r;
            e = *(float2*)&E2; va = vb; vb = *(float2*)&V3;
            r.x = sq * fabsf(e.x + va.y); r.y = sq * fabsf(e.y + vb.x); o2[2] = r;
            e = *(float2*)&E3; va = vb; vb = *(float2*)&V4;
            r.x = sq * fabsf(e.x + va.y); r.y = sq * fabsf(e.y + vb.x); o2[3] = r;
            e = *(float2*)&E4; va = *(float2*)&V4;
            r.x = sq * fabsf(e.x + va.y); r.y = sq * fabsf(e.y + vlast); o2[4] = r;
        }

        // stage next band's taps (epilogue never reads shD4)
        if (k + 1 < NB) {
            const float2* __restrict__ dsrc = (const float2*)d_D[bk + 1];
            for (int idx = tid; idx < DH; idx += 128) {
                float2 p = dsrc[idx];
                shD4[idx] = make_float4(p.x, p.x, p.y, p.y);
            }
        }
        __syncthreads();
    }
}

// ---------------------------------------------------------------------------
extern "C" void kernel_launch(void* const* d_in, const int* in_sizes, int n_in,
                              void* d_out, int out_size) {
    (void)in_sizes; (void)n_in; (void)out_size;
    const float* ts  = (const float*)d_in[0];
    const float* tr  = (const float*)d_in[1];
    const float* lsp = (const float*)d_in[2];
    const float* bwp = (const float*)d_in[3];
    float* out = (float*)d_out;

    float* bands = out + (size_t)BATCH * REG * NB * NOUT;

    k_prep<<<BATCH * NB, NPSI>>>(tr, lsp, bwp, bands);
    k_cwt<<<BATCH * REG, 128>>>(ts, out);
}

// round 6
// speedup vs baseline: 1.4868x; 1.0383x over previous
#include <cuda_runtime.h>
#include <math.h>

#define BATCH 8
#define REG   400
#define TLEN  1200
#define NB    5
#define NPSI  1024
#define LMAX  544

#define NOUT  TLEN
#define XOFF  288                  // left zero pad in shared X
#define SHX   1856
#define DMAX  576                  // padded taps per (b,k)
#define DH    288                  // tap pairs

static __device__ float d_D[BATCH * NB][DMAX];
static __device__ int   d_LD[BATCH * NB];   // L + 1 taps
static __device__ int   d_OFF[BATCH * NB];  // off - 1
static __device__ float d_SQS[BATCH * NB];  // sqrt(scale)

// ---------------------------------------------------------------------------
// packed fp32x2 helpers
// ---------------------------------------------------------------------------
__device__ __forceinline__ void fma2(unsigned long long &a,
                                     unsigned long long x,
                                     unsigned long long d) {
    asm("fma.rn.f32x2 %0, %1, %2, %0;" : "+l"(a) : "l"(x), "l"(d));
}
__device__ __forceinline__ unsigned long long lds64(unsigned sa) {
    unsigned long long v;
    asm("ld.shared.b64 %0, [%1];" : "=l"(v) : "r"(sa));
    return v;
}
__device__ __forceinline__ void lds128(unsigned sa, unsigned long long &a,
                                       unsigned long long &b) {
    asm("ld.shared.v2.u64 {%0,%1}, [%2];" : "=l"(a), "=l"(b) : "r"(sa));
}

// ---------------------------------------------------------------------------
// Kernel 1: INT_PSI (fp32 scan) + per-(b,k) taps + freq bands.
// ---------------------------------------------------------------------------
__global__ void k_prep(const float* __restrict__ tr,
                       const float* __restrict__ lsp,
                       const float* __restrict__ bwp,
                       float* __restrict__ out_bands) {
    __shared__ float sp[NPSI];
    __shared__ float shK[LMAX + 1];

    const int bk = blockIdx.x;
    const int b  = bk / NB;
    const int k  = bk % NB;
    const int i  = threadIdx.x;

    const float STEP_F = (float)(16.0 / 1023.0);

    {
        float x = -8.0f + STEP_F * (float)i;
        sp[i] = expf(-0.5f * x * x) * cosf(5.0f * x);
    }
    __syncthreads();
    for (int o = 1; o < NPSI; o <<= 1) {
        float add = (i >= o) ? sp[i - o] : 0.0f;
        __syncthreads();
        sp[i] += add;
        __syncthreads();
    }

    const float trf   = tr[b] / 2.0f;
    const float scale = expf(lsp[k]) / trf;
    const float sstep = scale * STEP_F;
    const int   L0    = (int)floorf(scale * 16.0f) + 2;

    bool m = false;
    if (i < LMAX) {
        int j = (int)floorf((float)i / sstep);
        m = (i < L0) && (j < NPSI);
        int jc = min(max(j, 0), NPSI - 1);
        shK[i] = m ? sp[jc] * STEP_F : 0.0f;
    } else if (i == LMAX) {
        shK[LMAX] = 0.0f;
    }
    const int L = __syncthreads_count(m);

    if (i <= L) {
        float prev = (i == 0) ? 0.0f : shK[i - 1];
        d_D[bk][i] = prev - shK[i];
    } else if (i < DMAX) {
        d_D[bk][i] = 0.0f;
    }

    if (i == 0) {
        d_LD[bk]  = L + 1;
        d_OFF[bk] = (L - 2) / 2 + 1 - L;
        d_SQS[bk] = sqrtf(scale);
        float center = 1.0f / (scale * tr[b]);
        float bw = bwp[k];
        out_bands[bk * 2 + 0] = fmaxf(0.008f, center * (1.0f - bw * 0.5f));
        out_bands[bk * 2 + 1] = fminf(0.12f,  center * (1.0f + bw * 0.5f));
    }
}

// ---------------------------------------------------------------------------
// Kernel 2: FIR, packed f32x2, polyphase-fused, software-pipelined D loads.
// Each step prefetches the NEXT step's (De,De,Do,Do) quad into the alternate
// register pair before issuing its own 10 FFMA2 -> LDS latency hidden.
// ---------------------------------------------------------------------------
__global__ void __launch_bounds__(128, 7)
k_cwt(const float* __restrict__ ts, float* __restrict__ out) {
    const int br  = blockIdx.x;
    const int b   = br / REG;
    const int tid = threadIdx.x;

    __shared__ __align__(16) float  shXA[SHX];
    __shared__ __align__(16) float  shXB[SHX + 2];
    __shared__ __align__(16) float4 shD4[DH];   // (De,De,Do,Do) per tap pair
    __shared__ float shV[129];

    for (int idx = tid; idx < SHX; idx += 128) shXA[idx] = 0.0f;
    for (int idx = tid; idx < SHX + 2; idx += 128) shXB[idx] = 0.0f;
    __syncthreads();
    const float* __restrict__ xrow = ts + (size_t)br * TLEN;
    for (int idx = tid; idx < TLEN; idx += 128) {
        float v = xrow[idx];
        shXA[XOFF + idx]     = v;
        shXB[XOFF + idx + 1] = v;      // shXB[m] = Xext[m-1]
    }
    // stage band 0's taps
    {
        const float2* __restrict__ dsrc = (const float2*)d_D[b * NB];
        for (int idx = tid; idx < DH; idx += 128) {
            float2 p = dsrc[idx];
            shD4[idx] = make_float4(p.x, p.x, p.y, p.y);
        }
    }
    __syncthreads();

    float* __restrict__ outbase = out + (size_t)br * NB * NOUT;

    const unsigned aXA = (unsigned)__cvta_generic_to_shared(shXA);
    const unsigned aXB = (unsigned)__cvta_generic_to_shared(shXB);
    const unsigned aD4 = (unsigned)__cvta_generic_to_shared(shD4);

    for (int k = 0; k < NB; k++) {
        const int   bk  = b * NB + k;
        const int   LD  = d_LD[bk];
        const int   off = d_OFF[bk];
        const float sq  = d_SQS[bk];

        const int  m0   = XOFF + off + 10 * tid;   // even-window base elem
        const bool even = ((m0 & 1) == 0);
        unsigned pX = even ? (aXA + 4u * (unsigned)m0)
                           : (aXB + 4u * (unsigned)(m0 + 1));
        unsigned pD = aD4;

        const int S  = (LD + 1) >> 1;              // tap pairs
        const int S6 = ((S + 5) / 6) * 6;          // zero-tap padded

        unsigned long long E0 = 0, E1 = 0, E2 = 0, E3 = 0, E4 = 0;
        unsigned long long V0 = 0, V1 = 0, V2 = 0, V3 = 0, V4 = 0;

        unsigned long long W0 = lds64(pX + 0);
        unsigned long long W1 = lds64(pX + 8);
        unsigned long long W2 = lds64(pX + 16);
        unsigned long long W3 = lds64(pX + 24);
        unsigned long long W4 = lds64(pX + 32);
        unsigned long long W5 = lds64(pX + 40);

        unsigned long long dEa, dOa, dEb, dOb;
        lds128(pD, dEa, dOa);                      // step-0 quad preload

#define FMAS(Q0, Q1, Q2, Q3, Q4, DE, DO)                                 \
        fma2(E0, Q0, DE); fma2(V0, Q0, DO);                              \
        fma2(E1, Q1, DE); fma2(V1, Q1, DO);                              \
        fma2(E2, Q2, DE); fma2(V2, Q2, DO);                              \
        fma2(E3, Q3, DE); fma2(V3, Q3, DO);                              \
        fma2(E4, Q4, DE); fma2(V4, Q4, DO);

        for (int it = 0; it < S6; it += 6) {
            lds128(pD + 16, dEb, dOb);             // prefetch step 1
            FMAS(W0, W1, W2, W3, W4, dEa, dOa)     // step 0
            W0 = lds64(pX + 48);
            lds128(pD + 32, dEa, dOa);             // prefetch step 2
            FMAS(W1, W2, W3, W4, W5, dEb, dOb)     // step 1
            W1 = lds64(pX + 56);
            lds128(pD + 48, dEb, dOb);             // prefetch step 3
            FMAS(W2, W3, W4, W5, W0, dEa, dOa)     // step 2
            W2 = lds64(pX + 64);
            lds128(pD + 64, dEa, dOa);             // prefetch step 4
            FMAS(W3, W4, W5, W0, W1, dEb, dOb)     // step 3
            W3 = lds64(pX + 72);
            lds128(pD + 80, dEb, dOb);             // prefetch step 5
            FMAS(W4, W5, W0, W1, W2, dEa, dOa)     // step 4
            W4 = lds64(pX + 80);
            lds128(pD + 96, dEa, dOa);             // prefetch next group step 0
            FMAS(W5, W0, W1, W2, W3, dEb, dOb)     // step 5
            W5 = lds64(pX + 88);

            pX += 48;
            pD += 96;
        }
#undef FMAS

        // exchange V0.lo with neighbor thread
        shV[tid] = ((float2*)&V0)->x;
        __syncthreads();

        if (tid < 120) {
            const float vlast = shV[tid + 1];   // V[10t+10]
            float2* __restrict__ o2 =
                (float2*)(outbase + (size_t)k * NOUT + 10 * tid);
            float2 e, va, vb, r;
            e = *(float2*)&E0; va = *(float2*)&V0; vb = *(float2*)&V1;
            r.x = sq * fabsf(e.x + va.y); r.y = sq * fabsf(e.y + vb.x); o2[0] = r;
            e = *(float2*)&E1; va = vb; vb = *(float2*)&V2;
            r.x = sq * fabsf(e.x + va.y); r.y = sq * fabsf(e.y + vb.x); o2[1] = r;
            e = *(float2*)&E2; va = vb; vb = *(float2*)&V3;
            r.x = sq * fabsf(e.x + va.y); r.y = sq * fabsf(e.y + vb.x); o2[2] = r;
            e = *(float2*)&E3; va = vb; vb = *(float2*)&V4;
            r.x = sq * fabsf(e.x + va.y); r.y = sq * fabsf(e.y + vb.x); o2[3] = r;
            e = *(float2*)&E4; va = *(float2*)&V4;
            r.x = sq * fabsf(e.x + va.y); r.y = sq * fabsf(e.y + vlast); o2[4] = r;
        }

        // stage next band's taps (epilogue never reads shD4)
        if (k + 1 < NB) {
            const float2* __restrict__ dsrc = (const float2*)d_D[bk + 1];
            for (int idx = tid; idx < DH; idx += 128) {
                float2 p = dsrc[idx];
                shD4[idx] = make_float4(p.x, p.x, p.y, p.y);
            }
        }
        __syncthreads();
    }
}

// ---------------------------------------------------------------------------
extern "C" void kernel_launch(void* const* d_in, const int* in_sizes, int n_in,
                              void* d_out, int out_size) {
    (void)in_sizes; (void)n_in; (void)out_size;
    const float* ts  = (const float*)d_in[0];
    const float* tr  = (const float*)d_in[1];
    const float* lsp = (const float*)d_in[2];
    const float* bwp = (const float*)d_in[3];
    float* out = (float*)d_out;

    float* bands = out + (size_t)BATCH * REG * NB * NOUT;

    k_prep<<<BATCH * NB, NPSI>>>(tr, lsp, bwp, bands);
    k_cwt<<<BATCH * REG, 128>>>(ts, out);
}

// round 7
// speedup vs baseline: 2.5019x; 1.6827x over previous
#include <cuda_runtime.h>
#include <math.h>

#define BATCH 8
#define REG   400
#define TLEN  1200
#define NB    5
#define NPSI  1024
#define LMAX  544

#define NOUT  TLEN
#define XOFF  288                  // left zero pad in shared X
#define SHX   1856
#define DMAX  576                  // padded taps per (b,k)
#define DH    288                  // tap pairs

static __device__ float d_D[BATCH * NB][DMAX];
static __device__ int   d_LD[BATCH * NB];   // kept tap count
static __device__ int   d_OFF[BATCH * NB];  // adjusted (off - 1)
static __device__ float d_SQS[BATCH * NB];  // sqrt(scale)

// ---------------------------------------------------------------------------
// packed fp32x2 helpers
// ---------------------------------------------------------------------------
__device__ __forceinline__ void fma2(unsigned long long &a,
                                     unsigned long long x,
                                     unsigned long long d) {
    asm("fma.rn.f32x2 %0, %1, %2, %0;" : "+l"(a) : "l"(x), "l"(d));
}
__device__ __forceinline__ unsigned long long lds64(unsigned sa) {
    unsigned long long v;
    asm("ld.shared.b64 %0, [%1];" : "=l"(v) : "r"(sa));
    return v;
}
__device__ __forceinline__ void lds128(unsigned sa, unsigned long long &a,
                                       unsigned long long &b) {
    asm("ld.shared.v2.u64 {%0,%1}, [%2];" : "=l"(a), "=l"(b) : "r"(sa));
}

// ---------------------------------------------------------------------------
// Kernel 1: INT_PSI (fp32 scan) + per-(b,k) taps + Gaussian-tail truncation
//           + freq bands.  576 threads per (b,k) block.
// ---------------------------------------------------------------------------
__global__ void k_prep(const float* __restrict__ tr,
                       const float* __restrict__ lsp,
                       const float* __restrict__ bwp,
                       float* __restrict__ out_bands) {
    __shared__ float sp[NPSI];
    __shared__ float shK[LMAX + 1];
    __shared__ float shDt[DMAX];
    __shared__ int   s_lo, s_hi;

    const int bk = blockIdx.x;
    const int b  = bk / NB;
    const int k  = bk % NB;
    const int i  = threadIdx.x;

    const float STEP_F = (float)(16.0 / 1023.0);

    // psi + inclusive scan (two values per thread since blockDim=576 < 1024)
    for (int idx = i; idx < NPSI; idx += DMAX) {
        float x = -8.0f + STEP_F * (float)idx;
        sp[idx] = expf(-0.5f * x * x) * cosf(5.0f * x);
    }
    __syncthreads();
    for (int o = 1; o < NPSI; o <<= 1) {
        float a0 = 0.0f, a1 = 0.0f;
        int i1 = i + DMAX;
        if (i >= o) a0 = sp[i - o];
        if (i1 < NPSI && i1 >= o) a1 = sp[i1 - o];
        __syncthreads();
        sp[i] += a0;
        if (i1 < NPSI) sp[i1] += a1;
        __syncthreads();
    }

    const float trf   = tr[b] / 2.0f;
    const float scale = expf(lsp[k]) / trf;
    const float sstep = scale * STEP_F;
    const int   L0    = (int)floorf(scale * 16.0f) + 2;

    bool m = false;
    if (i < LMAX) {
        int j = (int)floorf((float)i / sstep);
        m = (i < L0) && (j < NPSI);
        int jc = min(max(j, 0), NPSI - 1);
        shK[i] = m ? sp[jc] * STEP_F : 0.0f;
    } else if (i == LMAX) {
        shK[LMAX] = 0.0f;
    }
    if (i == 0) { s_lo = DMAX; s_hi = -1; }
    const int L = __syncthreads_count(m);   // mask is a prefix

    // full taps into shared
    float dv = 0.0f;
    if (i <= L) {
        float prev = (i == 0) ? 0.0f : shK[i - 1];
        dv = prev - shK[i];
    }
    shDt[i] = dv;
    __syncthreads();

    // significant range (exclude the boundary tap i == L; |D[L]| ~ 9.3e-6)
    const float thr = 1e-4f / scale;
    if (i < L && fabsf(shDt[i]) > thr) {
        atomicMin(&s_lo, i);
        atomicMax(&s_hi, i);
    }
    __syncthreads();

    int lo, hi;
    if (s_hi >= s_lo) { lo = s_lo & ~1; hi = s_hi; }
    else              { lo = 0;         hi = L;    }   // degenerate fallback
    const int newLD = hi - lo + 1;

    d_D[bk][i] = (i < newLD) ? shDt[i + lo] : 0.0f;    // i+lo <= hi < DMAX

    if (i == 0) {
        d_LD[bk]  = newLD;
        d_OFF[bk] = (L - 2) / 2 + 1 - L + lo;          // (off - 1) + lo
        d_SQS[bk] = sqrtf(scale);
        float center = 1.0f / (scale * tr[b]);
        float bw = bwp[k];
        out_bands[bk * 2 + 0] = fmaxf(0.008f, center * (1.0f - bw * 0.5f));
        out_bands[bk * 2 + 1] = fminf(0.12f,  center * (1.0f + bw * 0.5f));
    }
}

// ---------------------------------------------------------------------------
// Kernel 2: FIR, packed f32x2, polyphase-fused, software-pipelined D loads.
// (unchanged from R6 — at the RF-bank roofline; R7 reduces its workload)
// ---------------------------------------------------------------------------
__global__ void __launch_bounds__(128, 7)
k_cwt(const float* __restrict__ ts, float* __restrict__ out) {
    const int br  = blockIdx.x;
    const int b   = br / REG;
    const int tid = threadIdx.x;

    __shared__ __align__(16) float  shXA[SHX];
    __shared__ __align__(16) float  shXB[SHX + 2];
    __shared__ __align__(16) float4 shD4[DH];   // (De,De,Do,Do) per tap pair
    __shared__ float shV[129];

    for (int idx = tid; idx < SHX; idx += 128) shXA[idx] = 0.0f;
    for (int idx = tid; idx < SHX + 2; idx += 128) shXB[idx] = 0.0f;
    __syncthreads();
    const float* __restrict__ xrow = ts + (size_t)br * TLEN;
    for (int idx = tid; idx < TLEN; idx += 128) {
        float v = xrow[idx];
        shXA[XOFF + idx]     = v;
        shXB[XOFF + idx + 1] = v;      // shXB[m] = Xext[m-1]
    }
    // stage band 0's taps
    {
        const float2* __restrict__ dsrc = (const float2*)d_D[b * NB];
        for (int idx = tid; idx < DH; idx += 128) {
            float2 p = dsrc[idx];
            shD4[idx] = make_float4(p.x, p.x, p.y, p.y);
        }
    }
    __syncthreads();

    float* __restrict__ outbase = out + (size_t)br * NB * NOUT;

    const unsigned aXA = (unsigned)__cvta_generic_to_shared(shXA);
    const unsigned aXB = (unsigned)__cvta_generic_to_shared(shXB);
    const unsigned aD4 = (unsigned)__cvta_generic_to_shared(shD4);

    for (int k = 0; k < NB; k++) {
        const int   bk  = b * NB + k;
        const int   LD  = d_LD[bk];
        const int   off = d_OFF[bk];
        const float sq  = d_SQS[bk];

        const int  m0   = XOFF + off + 10 * tid;   // even-window base elem
        const bool even = ((m0 & 1) == 0);
        unsigned pX = even ? (aXA + 4u * (unsigned)m0)
                           : (aXB + 4u * (unsigned)(m0 + 1));
        unsigned pD = aD4;

        const int S  = (LD + 1) >> 1;              // tap pairs
        const int S6 = ((S + 5) / 6) * 6;          // zero-tap padded

        unsigned long long E0 = 0, E1 = 0, E2 = 0, E3 = 0, E4 = 0;
        unsigned long long V0 = 0, V1 = 0, V2 = 0, V3 = 0, V4 = 0;

        unsigned long long W0 = lds64(pX + 0);
        unsigned long long W1 = lds64(pX + 8);
        unsigned long long W2 = lds64(pX + 16);
        unsigned long long W3 = lds64(pX + 24);
        unsigned long long W4 = lds64(pX + 32);
        unsigned long long W5 = lds64(pX + 40);

        unsigned long long dEa, dOa, dEb, dOb;
        lds128(pD, dEa, dOa);                      // step-0 quad preload

#define FMAS(Q0, Q1, Q2, Q3, Q4, DE, DO)                                 \
        fma2(E0, Q0, DE); fma2(V0, Q0, DO);                              \
        fma2(E1, Q1, DE); fma2(V1, Q1, DO);                              \
        fma2(E2, Q2, DE); fma2(V2, Q2, DO);                              \
        fma2(E3, Q3, DE); fma2(V3, Q3, DO);                              \
        fma2(E4, Q4, DE); fma2(V4, Q4, DO);

        for (int it = 0; it < S6; it += 6) {
            lds128(pD + 16, dEb, dOb);             // prefetch step 1
            FMAS(W0, W1, W2, W3, W4, dEa, dOa)     // step 0
            W0 = lds64(pX + 48);
            lds128(pD + 32, dEa, dOa);             // prefetch step 2
            FMAS(W1, W2, W3, W4, W5, dEb, dOb)     // step 1
            W1 = lds64(pX + 56);
            lds128(pD + 48, dEb, dOb);             // prefetch step 3
            FMAS(W2, W3, W4, W5, W0, dEa, dOa)     // step 2
            W2 = lds64(pX + 64);
            lds128(pD + 64, dEa, dOa);             // prefetch step 4
            FMAS(W3, W4, W5, W0, W1, dEb, dOb)     // step 3
            W3 = lds64(pX + 72);
            lds128(pD + 80, dEb, dOb);             // prefetch step 5
            FMAS(W4, W5, W0, W1, W2, dEa, dOa)     // step 4
            W4 = lds64(pX + 80);
            lds128(pD + 96, dEa, dOa);             // prefetch next group step 0
            FMAS(W5, W0, W1, W2, W3, dEb, dOb)     // step 5
            W5 = lds64(pX + 88);

            pX += 48;
            pD += 96;
        }
#undef FMAS

        // exchange V0.lo with neighbor thread
        shV[tid] = ((float2*)&V0)->x;
        __syncthreads();

        if (tid < 120) {
            const float vlast = shV[tid + 1];   // V[10t+10]
            float2* __restrict__ o2 =
                (float2*)(outbase + (size_t)k * NOUT + 10 * tid);
            float2 e, va, vb, r;
            e = *(float2*)&E0; va = *(float2*)&V0; vb = *(float2*)&V1;
            r.x = sq * fabsf(e.x + va.y); r.y = sq * fabsf(e.y + vb.x); o2[0] = r;
            e = *(float2*)&E1; va = vb; vb = *(float2*)&V2;
            r.x = sq * fabsf(e.x + va.y); r.y = sq * fabsf(e.y + vb.x); o2[1] = r;
            e = *(float2*)&E2; va = vb; vb = *(float2*)&V3;
            r.x = sq * fabsf(e.x + va.y); r.y = sq * fabsf(e.y + vb.x); o2[2] = r;
            e = *(float2*)&E3; va = vb; vb = *(float2*)&V4;
            r.x = sq * fabsf(e.x + va.y); r.y = sq * fabsf(e.y + vb.x); o2[3] = r;
            e = *(float2*)&E4; va = *(float2*)&V4;
            r.x = sq * fabsf(e.x + va.y); r.y = sq * fabsf(e.y + vlast); o2[4] = r;
        }

        // stage next band's taps (epilogue never reads shD4)
        if (k + 1 < NB) {
            const float2* __restrict__ dsrc = (const float2*)d_D[bk + 1];
            for (int idx = tid; idx < DH; idx += 128) {
                float2 p = dsrc[idx];
                shD4[idx] = make_float4(p.x, p.x, p.y, p.y);
            }
        }
        __syncthreads();
    }
}

// ---------------------------------------------------------------------------
extern "C" void kernel_launch(void* const* d_in, const int* in_sizes, int n_in,
                              void* d_out, int out_size) {
    (void)in_sizes; (void)n_in; (void)out_size;
    const float* ts  = (const float*)d_in[0];
    const float* tr  = (const float*)d_in[1];
    const float* lsp = (const float*)d_in[2];
    const float* bwp = (const float*)d_in[3];
    float* out = (float*)d_out;

    float* bands = out + (size_t)BATCH * REG * NB * NOUT;

    k_prep<<<BATCH * NB, DMAX>>>(tr, lsp, bwp, bands);
    k_cwt<<<BATCH * REG, 128>>>(ts, out);
}